// round 15
// baseline (speedup 1.0000x reference)
#include <cuda_runtime.h>
#include <cuda_fp16.h>
#include <math.h>
#include <stdint.h>

// Problem dims
#define Bdim 128
#define Tdim 64
#define NAa  10
#define NVv  16
#define Kk   4
#define SDd  512
#define Hh   256
#define Ee   32
#define ROWS (Bdim * Tdim)        // 8192
#define NCAT 844                  // real concat width
#define NCATP 896                 // padded to 14*64
#define N2   544                  // (NV+1)*E
#define MIDW 1024                 // MID: [0,256) w00com | [256,512) w00mod | [512,768) w1in | [768,1024) w2in
#define K2   1024                 // GEMM2 full K
#define N2P2 640                  // GEMM2 padded N: 544 w1 | 32 w2 | 4 w00c | 4 w00m | pad
#define N2V  584                  // valid GEMM2 cols

// ---------------- scratch (__device__ globals; no cudaMalloc) ----------------
__device__ float g_H1[(size_t)ROWS * NCAT];            // only cols [768,844) written/read
__device__ __align__(16) __half g_W1F16[(size_t)ROWS * N2P2]; // |GEMM2 out| fp16
__device__ __align__(16) __half g_ST [(size_t)ROWS * SDd];    // states fp16
__device__ __align__(16) __half g_MID[(size_t)ROWS * MIDW];   // relu variants fp16
__device__ __align__(16) __half g_BT [(size_t)NCATP * SDd];   // B^T GEMM1 [c][k]
__device__ __align__(16) __half g_B2T[(size_t)N2P2 * K2];     // B^T GEMM2 block-diagonal
__device__ float g_biascat[NCATP];
__device__ float g_bias2[N2P2];
__device__ float g_hdelta[Hh];
__device__ float g_gdelta[1];

// ---------------- helpers ----------------
__device__ __forceinline__ uint32_t smem_u32(const void* p) {
    uint32_t a;
    asm("{ .reg .u64 t; cvta.to.shared.u64 t, %1; cvt.u32.u64 %0, t; }" : "=r"(a) : "l"(p));
    return a;
}
__device__ __forceinline__ void ldsm_x4(uint32_t* r, uint32_t addr) {
    asm volatile("ldmatrix.sync.aligned.m8n8.x4.shared.b16 {%0,%1,%2,%3}, [%4];"
                 : "=r"(r[0]), "=r"(r[1]), "=r"(r[2]), "=r"(r[3]) : "r"(addr));
}
__device__ __forceinline__ void mma_f16(float* c, const uint32_t* a, const uint32_t* b) {
    asm volatile("mma.sync.aligned.m16n8k16.row.col.f32.f16.f16.f32 "
                 "{%0,%1,%2,%3}, {%4,%5,%6,%7}, {%8,%9}, {%0,%1,%2,%3};"
                 : "+f"(c[0]), "+f"(c[1]), "+f"(c[2]), "+f"(c[3])
                 : "r"(a[0]), "r"(a[1]), "r"(a[2]), "r"(a[3]), "r"(b[0]), "r"(b[1]));
}
#define CP_ASYNC16(dst, src) \
    asm volatile("cp.async.cg.shared.global [%0], [%1], 16;" :: "r"(dst), "l"(src))
#define CP_COMMIT() asm volatile("cp.async.commit_group;" ::: "memory")
#define CP_WAIT(n)  asm volatile("cp.async.wait_group %0;" :: "n"(n) : "memory")

__device__ __forceinline__ uint32_t pack_h2(float a, float b) {
    __half h0 = __float2half(a), h1 = __float2half(b);
    return (uint32_t)__half_as_ushort(h0) | ((uint32_t)__half_as_ushort(h1) << 16);
}

// ---------------- merged prep kernel ----------------
#define N_SPLIT (ROWS * SDd / 4)      // 1048576
#define N_P1    (NCATP * SDd)         // 458752
#define N_P2    (N2P2 * K2)           // 655360
#define N_PREP  (N_SPLIT + N_P1 + N_P2)

__global__ void prep_kernel(
    const float* __restrict__ states,
    const float* __restrict__ w00_l1_W, const float* __restrict__ w00_l1_b,
    const float* __restrict__ w1_l1_W,  const float* __restrict__ w1_l1_b,
    const float* __restrict__ w2_l1_W,  const float* __restrict__ w2_l1_b,
    const float* __restrict__ w01_W,    const float* __restrict__ w01_b,
    const float* __restrict__ b01_W,    const float* __restrict__ b01_b,
    const float* __restrict__ b00_W,    const float* __restrict__ b00_b,
    const float* __restrict__ b1_W,     const float* __restrict__ b1_b,
    const float* __restrict__ b2_l1_W,  const float* __restrict__ b2_l1_b,
    const float* __restrict__ w1_l2_W,  const float* __restrict__ w1_l2_b,
    const float* __restrict__ w2_l2_W,  const float* __restrict__ w2_l2_b,
    const float* __restrict__ w00_l2_W, const float* __restrict__ w00_l2_b)
{
    int gidx = blockIdx.x * blockDim.x + threadIdx.x;

    if (gidx < N_SPLIT) {
        float4 v = ((const float4*)states)[gidx];
        __half h0 = __float2half(v.x), h1 = __float2half(v.y);
        __half h2 = __float2half(v.z), h3 = __float2half(v.w);
        uint32_t hA = (uint32_t)__half_as_ushort(h0) | ((uint32_t)__half_as_ushort(h1) << 16);
        uint32_t hB = (uint32_t)__half_as_ushort(h2) | ((uint32_t)__half_as_ushort(h3) << 16);
        ((uint2*)g_ST)[gidx] = make_uint2(hA, hB);
        return;
    }
    int idx = gidx - N_SPLIT;
    if (idx < N_P1) {
        int c = idx / SDd;
        int k = idx - c * SDd;
        float v = 0.f;
        if (c < NCAT) {
            if      (c < 256) v = w00_l1_W[k * 256 + c];
            else if (c < 512) v = w1_l1_W[k * 256 + (c - 256)];
            else if (c < 768) v = w2_l1_W[k * 256 + (c - 512)];
            else if (c < 778) v = w01_W[k * 10 + (c - 768)];
            else if (c == 778) v = b01_W[k];
            else if (c == 779) v = b00_W[k];
            else if (c < 812) v = b1_W[k * 32 + (c - 780)];
            else              v = b2_l1_W[k * 32 + (c - 812)];
        }
        g_BT[idx] = __float2half(v);

        if (idx < NCATP) {
            int cc = idx;
            float bv = 0.f;
            if (cc < NCAT) {
                if      (cc < 256) bv = w00_l1_b[cc];
                else if (cc < 512) bv = w1_l1_b[cc - 256];
                else if (cc < 768) bv = w2_l1_b[cc - 512];
                else if (cc < 778) bv = w01_b[cc - 768];
                else if (cc == 778) bv = b01_b[0];
                else if (cc == 779) bv = b00_b[0];
                else if (cc < 812) bv = b1_b[cc - 780];
                else               bv = b2_l1_b[cc - 812];
            }
            g_biascat[cc] = bv;
        }
        if (idx < Hh) {
            float s = 0.f;
            #pragma unroll
            for (int j = 0; j < NVv; j++) s += w00_l1_W[(SDd + j) * 256 + idx];
            g_hdelta[idx] = s;
        }
        if (idx == Hh) {
            float s = 0.f;
            #pragma unroll
            for (int j = 0; j < NVv; j++) s += b00_W[SDd + j];
            g_gdelta[0] = s;
        }
        return;
    }
    idx -= N_P1;
    if (idx < N_P2) {
        int c = idx / K2;
        int k = idx - c * K2;
        float v = 0.f;
        if (c < N2) {                    // w1: K rows [512,768)
            if (k >= 512 && k < 768) v = w1_l2_W[(k - 512) * N2 + c];
        } else if (c < 576) {            // w2: K rows [768,1024)
            if (k >= 768) v = w2_l2_W[(k - 768) * Ee + (c - N2)];
        } else if (c < 580) {            // w00 common: K rows [0,256)
            if (k < 256) v = w00_l2_W[k * 4 + (c - 576)];
        } else if (c < 584) {            // w00 mod: K rows [256,512)
            if (k >= 256 && k < 512) v = w00_l2_W[(k - 256) * 4 + (c - 580)];
        }
        g_B2T[idx] = __float2half(v);
        if (idx < N2P2) {
            int cc = idx;
            float bv = 0.f;
            if (cc < N2)       bv = w1_l2_b[cc];
            else if (cc < 576) bv = w2_l2_b[cc - N2];
            else if (cc < 580) bv = w00_l2_b[cc - 576];
            else if (cc < 584) bv = w00_l2_b[cc - 580];
            g_bias2[cc] = bv;
        }
    }
}

// ---------------------------------------------------------------------------
// mma.sync fp16 GEMM, 2-stage cp.async smem pipeline + double-buffered
// register fragments.  MODE 0: GEMM1 (fp32 tail store + relu-fp16 MID with
// w00 common/mod variants).  MODE 1: GEMM2 block-diagonal with per-tile
// K-windows, |out| stored fp16 to g_W1F16.
// ---------------------------------------------------------------------------
#define SROW    144
#define OF_A    0
#define OF_B    (128 * SROW)            // 18432
#define STAGE   (OF_B + 64 * SROW)      // 27648
#define SMTOT   (2 * STAGE)             // 55296

__device__ __forceinline__ void load_a_frags(uint32_t stb, int ks, uint32_t a[2][4],
                                             int wm, int lane) {
    #pragma unroll
    for (int mt = 0; mt < 2; mt++) {
        int ar = wm * 32 + mt * 16 + (lane & 15);
        int ak = ks * 16 + (lane >> 4) * 8;
        ldsm_x4(a[mt], stb + OF_A + (uint32_t)(ar * SROW + ak * 2));
    }
}
__device__ __forceinline__ void load_b_frags(uint32_t stb, int ks, uint32_t b[4][2],
                                             int wn, int lane) {
    #pragma unroll
    for (int jp = 0; jp < 2; jp++) {
        int tilei = lane >> 3, rin = lane & 7;
        int nrow = wn * 32 + jp * 16 + (tilei >> 1) * 8 + rin;
        int kof  = ks * 16 + (tilei & 1) * 8;
        uint32_t r[4];
        ldsm_x4(r, stb + OF_B + (uint32_t)(nrow * SROW + kof * 2));
        b[jp*2][0] = r[0]; b[jp*2][1] = r[1];
        b[jp*2+1][0] = r[2]; b[jp*2+1][1] = r[3];
    }
}

template <int MODE>
__global__ void __launch_bounds__(256)
gemm_mma(const __half* __restrict__ A, int lda,
         const __half* __restrict__ B, int ldb,
         const float* __restrict__ bias,
         float* __restrict__ C, int ldc, int Nvalid, int Kfull)
{
    extern __shared__ char smem[];
    const uint32_t sb = smem_u32(smem);
    const int tid  = threadIdx.x;
    const int w    = tid >> 5;
    const int lane = tid & 31;
    const int wm   = w & 3;
    const int wn   = w >> 2;
    const int bm   = blockIdx.y * 128;
    const int bn   = blockIdx.x * 64;

    int kb = 0, klen = Kfull;
    if (MODE == 1) {
        if (bn + 64 <= 512)      { kb = 512; klen = 256; }   // dense w1 tiles
        else if (bn < 576)       { kb = 512; klen = 512; }   // mixed w1/w2 tile
        else                     { kb = 0;   klen = 512; }   // w00 tile
    }

    float acc[2][4][4];
    #pragma unroll
    for (int mt = 0; mt < 2; mt++)
        #pragma unroll
        for (int nt = 0; nt < 4; nt++)
            #pragma unroll
            for (int i = 0; i < 4; i++) acc[mt][nt][i] = 0.f;

    const int nch = klen >> 6;
    const int arow = tid >> 3, asec = tid & 7;

    #define ISSUE_LOADS(c_, s_) do {                                             \
        const int k0_ = kb + ((c_) << 6);                                        \
        const uint32_t base_ = sb + (s_) * STAGE;                                \
        _Pragma("unroll")                                                        \
        for (int i = 0; i < 4; i++) {                                            \
            int row_ = arow + i * 32;                                            \
            uint32_t so_ = base_ + row_ * SROW + asec * 16;                      \
            const size_t go_ = (size_t)(bm + row_) * lda + k0_ + asec * 8;       \
            CP_ASYNC16(so_ + OF_A, (const char*)(A + go_));                      \
        }                                                                        \
        _Pragma("unroll")                                                        \
        for (int i = 0; i < 2; i++) {                                            \
            int row_ = arow + i * 32;                                            \
            uint32_t so_ = base_ + row_ * SROW + asec * 16;                      \
            const size_t go_ = (size_t)(bn + row_) * ldb + k0_ + asec * 8;       \
            CP_ASYNC16(so_ + OF_B, (const char*)(B + go_));                      \
        }                                                                        \
        CP_COMMIT();                                                             \
    } while (0)

    ISSUE_LOADS(0, 0);

    for (int c = 0; c < nch; c++) {
        if (c + 1 < nch) { ISSUE_LOADS(c + 1, (c + 1) & 1); CP_WAIT(1); }
        else             { CP_WAIT(0); }
        __syncthreads();

        const uint32_t stb = sb + (c & 1) * STAGE;

        uint32_t ah[2][2][4], bh[2][4][2];
        load_a_frags(stb, 0, ah[0], wm, lane);
        load_b_frags(stb, 0, bh[0], wn, lane);

        #pragma unroll
        for (int ks = 0; ks < 4; ks++) {
            const int cur = ks & 1;
            if (ks < 3) {
                load_a_frags(stb, ks + 1, ah[cur ^ 1], wm, lane);
                load_b_frags(stb, ks + 1, bh[cur ^ 1], wn, lane);
            }
            #pragma unroll
            for (int mt = 0; mt < 2; mt++)
                #pragma unroll
                for (int nt = 0; nt < 4; nt++)
                    mma_f16(acc[mt][nt], ah[cur][mt], bh[cur][nt]);
        }
        __syncthreads();
    }

    // Epilogue
    const int trow  = lane >> 2;
    const int tcol2 = (lane & 3) * 2;
    #pragma unroll
    for (int mt = 0; mt < 2; mt++) {
        #pragma unroll
        for (int nt = 0; nt < 4; nt++) {
            int col = bn + wn * 32 + nt * 8 + tcol2;
            float bv0 = bias[col], bv1 = bias[col + 1];
            #pragma unroll
            for (int half = 0; half < 2; half++) {
                int row = bm + wm * 32 + mt * 16 + trow + half * 8;
                float v0 = acc[mt][nt][half * 2 + 0] + bv0;
                float v1 = acc[mt][nt][half * 2 + 1] + bv1;
                if (MODE == 0) {
                    if (col < 256) {
                        // common relu -> MID[col]; modified relu -> MID[col+256]
                        ((uint32_t*)g_MID)[((size_t)row * MIDW + col) >> 1] =
                            pack_h2(fmaxf(v0, 0.f), fmaxf(v1, 0.f));
                        float d0 = g_hdelta[col], d1 = g_hdelta[col + 1];
                        ((uint32_t*)g_MID)[((size_t)row * MIDW + col + 256) >> 1] =
                            pack_h2(fmaxf(v0 + d0, 0.f), fmaxf(v1 + d1, 0.f));
                    } else if (col < 768) {
                        ((uint32_t*)g_MID)[((size_t)row * MIDW + col + 256) >> 1] =
                            pack_h2(fmaxf(v0, 0.f), fmaxf(v1, 0.f));
                    } else if (col < Nvalid) {
                        *(float2*)(C + (size_t)row * ldc + col) = make_float2(v0, v1);
                    }
                } else {
                    if (col < Nvalid)
                        ((uint32_t*)g_W1F16)[((size_t)row * N2P2 + col) >> 1] =
                            pack_h2(fabsf(v0), fabsf(v1));
                }
            }
        }
    }
}

// ---------------------------------------------------------------------------
// Final fused kernel: one warp per row (now tiny: W1F16 row + H1 tail cols).
// ---------------------------------------------------------------------------
__global__ void __launch_bounds__(256)
final_kernel(const float* __restrict__ qvals,
             const int*   __restrict__ cr,
             const float* __restrict__ b2_l2_W,   // (32,1)
             const float* __restrict__ b2_l2_b,   // (1)
             float* __restrict__ out)
{
    __shared__ float s_q[8][NAa];

    const int w = threadIdx.x >> 5;
    const int l = threadIdx.x & 31;
    const int r = blockIdx.x * 8 + w;
    const int b = r >> 6;                 // batch index (T = 64)
    const float* __restrict__ row = g_H1 + (size_t)r * NCAT;

    if (l < NAa) s_q[w][l] = qvals[r * NAa + l];
    __syncwarp();

    const bool mod = (b < NVv);
    const __half* __restrict__ w1r = g_W1F16 + (size_t)r * N2P2;

    // w00 (already |.| with bias): common at 576-579, modified at 580-583
    float w0c[4], w0m[4];
    #pragma unroll
    for (int o = 0; o < 4; o++) {
        w0c[o] = __half2float(w1r[576 + o]);
        w0m[o] = __half2float(w1r[580 + o]);
    }

    float w2a = __half2float(w1r[N2 + l]);

    float xb2 = fmaxf(row[812 + l], 0.f) * b2_l2_W[l];
    #pragma unroll
    for (int off = 16; off; off >>= 1) xb2 += __shfl_xor_sync(0xffffffffu, xb2, off);
    float b2 = xb2 + b2_l2_b[0];

    float b1v = row[780 + l];

    float gq_l;
    if (l < NVv) {
        const int* __restrict__ crr = cr + (size_t)r * (Kk * NVv);
        float g = 0.f;
        #pragma unroll
        for (int k = 0; k < Kk; k++) {
            int idx = crr[k * NVv + l];
            float wk = (mod && l == b) ? w0m[k] : w0c[k];
            g += s_q[w][idx] * wk;
        }
        g += row[779];
        if (mod && l == b) g += g_gdelta[0];
        gq_l = g;
    } else {
        float oth = row[778];
        #pragma unroll
        for (int a = 0; a < NAa; a++) oth += s_q[w][a] * row[768 + a];
        gq_l = oth;
    }

    // hidden = elu(gq @ |w1| + b1) — w1r already |.|
    float accH = b1v;
    #pragma unroll
    for (int v = 0; v <= NVv; v++) {
        float gqv = __shfl_sync(0xffffffffu, gq_l, v);
        accH += gqv * __half2float(w1r[v * Ee + l]);
    }
    float hidden = (accH > 0.f) ? accH : expm1f(accH);

    float part = hidden * w2a;
    #pragma unroll
    for (int off = 16; off; off >>= 1) part += __shfl_xor_sync(0xffffffffu, part, off);
    if (l == 0) out[r] = part + b2;
}

// ---------------------------------------------------------------------------
extern "C" void kernel_launch(void* const* d_in, const int* in_sizes, int n_in,
                              void* d_out, int out_size)
{
    const float* qvals    = (const float*)d_in[0];
    const int*   cr       = (const int*)  d_in[1];
    const float* states   = (const float*)d_in[2];
    const float* w00_l1_W = (const float*)d_in[3];
    const float* w00_l1_b = (const float*)d_in[4];
    const float* w00_l2_W = (const float*)d_in[5];
    const float* w00_l2_b = (const float*)d_in[6];
    const float* b00_W    = (const float*)d_in[7];
    const float* b00_b    = (const float*)d_in[8];
    const float* w01_W    = (const float*)d_in[9];
    const float* w01_b    = (const float*)d_in[10];
    const float* b01_W    = (const float*)d_in[11];
    const float* b01_b    = (const float*)d_in[12];
    const float* w1_l1_W  = (const float*)d_in[13];
    const float* w1_l1_b  = (const float*)d_in[14];
    const float* w1_l2_W  = (const float*)d_in[15];
    const float* w1_l2_b  = (const float*)d_in[16];
    const float* b1_W     = (const float*)d_in[17];
    const float* b1_b     = (const float*)d_in[18];
    const float* w2_l1_W  = (const float*)d_in[19];
    const float* w2_l1_b  = (const float*)d_in[20];
    const float* w2_l2_W  = (const float*)d_in[21];
    const float* w2_l2_b  = (const float*)d_in[22];
    const float* b2_l1_W  = (const float*)d_in[23];
    const float* b2_l1_b  = (const float*)d_in[24];
    const float* b2_l2_W  = (const float*)d_in[25];
    const float* b2_l2_b  = (const float*)d_in[26];
    float* out = (float*)d_out;

    static int attr_done = 0;
    if (!attr_done) {
        cudaFuncSetAttribute(gemm_mma<0>, cudaFuncAttributeMaxDynamicSharedMemorySize, SMTOT);
        cudaFuncSetAttribute(gemm_mma<1>, cudaFuncAttributeMaxDynamicSharedMemorySize, SMTOT);
        attr_done = 1;
    }

    float *H1, *biascat, *bias2;
    __half *ST, *MID, *BT, *B2T;
    cudaGetSymbolAddress((void**)&H1,      g_H1);
    cudaGetSymbolAddress((void**)&biascat, g_biascat);
    cudaGetSymbolAddress((void**)&bias2,   g_bias2);
    cudaGetSymbolAddress((void**)&ST,      g_ST);
    cudaGetSymbolAddress((void**)&MID,     g_MID);
    cudaGetSymbolAddress((void**)&BT,      g_BT);
    cudaGetSymbolAddress((void**)&B2T,     g_B2T);

    // 1) merged precompute
    prep_kernel<<<(N_PREP + 255) / 256, 256>>>(
        states,
        w00_l1_W, w00_l1_b, w1_l1_W, w1_l1_b, w2_l1_W, w2_l1_b,
        w01_W, w01_b, b01_W, b01_b, b00_W, b00_b, b1_W, b1_b, b2_l1_W, b2_l1_b,
        w1_l2_W, w1_l2_b, w2_l2_W, w2_l2_b, w00_l2_W, w00_l2_b);

    // 2) GEMM1: relu variants -> MID, fp32 tail cols -> H1
    {
        dim3 grid(NCATP / 64, ROWS / 128);
        gemm_mma<0><<<grid, 256, SMTOT>>>(ST, SDd, BT, SDd,
                                          biascat, H1, NCAT, NCAT, SDd);
    }

    // 3) GEMM2 (block-diagonal, per-tile K-windows): |out| fp16 -> g_W1F16
    {
        dim3 grid(N2P2 / 64, ROWS / 128);
        gemm_mma<1><<<grid, 256, SMTOT>>>(MID, MIDW, B2T, K2,
                                          bias2, nullptr, 0, N2V, K2);
    }

    // 4) fused epilogue
    final_kernel<<<ROWS / 8, 256>>>(qvals, cr, b2_l2_W, b2_l2_b, out);
}

// round 16
// speedup vs baseline: 1.0270x; 1.0270x over previous
#include <cuda_runtime.h>
#include <cuda_fp16.h>
#include <math.h>
#include <stdint.h>

// Problem dims
#define Bdim 128
#define Tdim 64
#define NAa  10
#define NVv  16
#define Kk   4
#define SDd  512
#define Hh   256
#define Ee   32
#define ROWS (Bdim * Tdim)        // 8192
#define NCAT 844                  // real concat width
#define NCATP 896                 // padded to 14*64
#define N2   544                  // (NV+1)*E
#define MIDW 768                  // MID: [0,256) w00in | [256,512) w1in | [512,768) w2in
#define K2   768                  // GEMM2 full K
#define N2P2 640                  // GEMM2 padded N: 544 w1 | 32 w2 | 4 w00c | pad
#define N2V  580                  // valid GEMM2 cols
#define MODROWS 1024              // rows needing the w00-mod path (b < NV)

// ---------------- scratch (__device__ globals; no cudaMalloc) ----------------
__device__ float g_H1[(size_t)ROWS * NCAT];            // cols [768,844) all rows; [0,256) rows<1024
__device__ __align__(16) __half g_W1F16[(size_t)ROWS * N2P2]; // |GEMM2 out| fp16
__device__ __align__(16) __half g_ST [(size_t)ROWS * SDd];    // states fp16
__device__ __align__(16) __half g_MID[(size_t)ROWS * MIDW];   // relu fp16
__device__ __align__(16) __half g_BT [(size_t)NCATP * SDd];   // B^T GEMM1 [c][k]
__device__ __align__(16) __half g_B2T[(size_t)N2P2 * K2];     // B^T GEMM2 block-diagonal
__device__ float g_biascat[NCATP];
__device__ float g_bias2[N2P2];
__device__ float g_hdelta[Hh];
__device__ float g_gdelta[1];

// ---------------- helpers ----------------
__device__ __forceinline__ uint32_t smem_u32(const void* p) {
    uint32_t a;
    asm("{ .reg .u64 t; cvta.to.shared.u64 t, %1; cvt.u32.u64 %0, t; }" : "=r"(a) : "l"(p));
    return a;
}
__device__ __forceinline__ void ldsm_x4(uint32_t* r, uint32_t addr) {
    asm volatile("ldmatrix.sync.aligned.m8n8.x4.shared.b16 {%0,%1,%2,%3}, [%4];"
                 : "=r"(r[0]), "=r"(r[1]), "=r"(r[2]), "=r"(r[3]) : "r"(addr));
}
__device__ __forceinline__ void mma_f16(float* c, const uint32_t* a, const uint32_t* b) {
    asm volatile("mma.sync.aligned.m16n8k16.row.col.f32.f16.f16.f32 "
                 "{%0,%1,%2,%3}, {%4,%5,%6,%7}, {%8,%9}, {%0,%1,%2,%3};"
                 : "+f"(c[0]), "+f"(c[1]), "+f"(c[2]), "+f"(c[3])
                 : "r"(a[0]), "r"(a[1]), "r"(a[2]), "r"(a[3]), "r"(b[0]), "r"(b[1]));
}
#define CP_ASYNC16(dst, src) \
    asm volatile("cp.async.cg.shared.global [%0], [%1], 16;" :: "r"(dst), "l"(src))
#define CP_COMMIT() asm volatile("cp.async.commit_group;" ::: "memory")
#define CP_WAIT(n)  asm volatile("cp.async.wait_group %0;" :: "n"(n) : "memory")

__device__ __forceinline__ uint32_t pack_h2(float a, float b) {
    __half h0 = __float2half(a), h1 = __float2half(b);
    return (uint32_t)__half_as_ushort(h0) | ((uint32_t)__half_as_ushort(h1) << 16);
}

// ---------------- merged prep kernel ----------------
#define N_SPLIT (ROWS * SDd / 4)      // 1048576
#define N_P1    (NCATP * SDd)         // 458752
#define N_P2    (N2P2 * K2)           // 491520
#define N_PREP  (N_SPLIT + N_P1 + N_P2)

__global__ void prep_kernel(
    const float* __restrict__ states,
    const float* __restrict__ w00_l1_W, const float* __restrict__ w00_l1_b,
    const float* __restrict__ w1_l1_W,  const float* __restrict__ w1_l1_b,
    const float* __restrict__ w2_l1_W,  const float* __restrict__ w2_l1_b,
    const float* __restrict__ w01_W,    const float* __restrict__ w01_b,
    const float* __restrict__ b01_W,    const float* __restrict__ b01_b,
    const float* __restrict__ b00_W,    const float* __restrict__ b00_b,
    const float* __restrict__ b1_W,     const float* __restrict__ b1_b,
    const float* __restrict__ b2_l1_W,  const float* __restrict__ b2_l1_b,
    const float* __restrict__ w1_l2_W,  const float* __restrict__ w1_l2_b,
    const float* __restrict__ w2_l2_W,  const float* __restrict__ w2_l2_b,
    const float* __restrict__ w00_l2_W, const float* __restrict__ w00_l2_b)
{
    int gidx = blockIdx.x * blockDim.x + threadIdx.x;

    if (gidx < N_SPLIT) {
        float4 v = ((const float4*)states)[gidx];
        __half h0 = __float2half(v.x), h1 = __float2half(v.y);
        __half h2 = __float2half(v.z), h3 = __float2half(v.w);
        uint32_t hA = (uint32_t)__half_as_ushort(h0) | ((uint32_t)__half_as_ushort(h1) << 16);
        uint32_t hB = (uint32_t)__half_as_ushort(h2) | ((uint32_t)__half_as_ushort(h3) << 16);
        ((uint2*)g_ST)[gidx] = make_uint2(hA, hB);
        return;
    }
    int idx = gidx - N_SPLIT;
    if (idx < N_P1) {
        int c = idx / SDd;
        int k = idx - c * SDd;
        float v = 0.f;
        if (c < NCAT) {
            if      (c < 256) v = w00_l1_W[k * 256 + c];
            else if (c < 512) v = w1_l1_W[k * 256 + (c - 256)];
            else if (c < 768) v = w2_l1_W[k * 256 + (c - 512)];
            else if (c < 778) v = w01_W[k * 10 + (c - 768)];
            else if (c == 778) v = b01_W[k];
            else if (c == 779) v = b00_W[k];
            else if (c < 812) v = b1_W[k * 32 + (c - 780)];
            else              v = b2_l1_W[k * 32 + (c - 812)];
        }
        g_BT[idx] = __float2half(v);

        if (idx < NCATP) {
            int cc = idx;
            float bv = 0.f;
            if (cc < NCAT) {
                if      (cc < 256) bv = w00_l1_b[cc];
                else if (cc < 512) bv = w1_l1_b[cc - 256];
                else if (cc < 768) bv = w2_l1_b[cc - 512];
                else if (cc < 778) bv = w01_b[cc - 768];
                else if (cc == 778) bv = b01_b[0];
                else if (cc == 779) bv = b00_b[0];
                else if (cc < 812) bv = b1_b[cc - 780];
                else               bv = b2_l1_b[cc - 812];
            }
            g_biascat[cc] = bv;
        }
        if (idx < Hh) {
            float s = 0.f;
            #pragma unroll
            for (int j = 0; j < NVv; j++) s += w00_l1_W[(SDd + j) * 256 + idx];
            g_hdelta[idx] = s;
        }
        if (idx == Hh) {
            float s = 0.f;
            #pragma unroll
            for (int j = 0; j < NVv; j++) s += b00_W[SDd + j];
            g_gdelta[0] = s;
        }
        return;
    }
    idx -= N_P1;
    if (idx < N_P2) {
        int c = idx / K2;
        int k = idx - c * K2;
        float v = 0.f;
        if (c < N2) {                    // w1: K rows [256,512)
            if (k >= 256 && k < 512) v = w1_l2_W[(k - 256) * N2 + c];
        } else if (c < 576) {            // w2: K rows [512,768)
            if (k >= 512) v = w2_l2_W[(k - 512) * Ee + (c - N2)];
        } else if (c < 580) {            // w00 common: K rows [0,256)
            if (k < 256) v = w00_l2_W[k * 4 + (c - 576)];
        }
        g_B2T[idx] = __float2half(v);
        if (idx < N2P2) {
            int cc = idx;
            float bv = 0.f;
            if (cc < N2)       bv = w1_l2_b[cc];
            else if (cc < 576) bv = w2_l2_b[cc - N2];
            else if (cc < 580) bv = w00_l2_b[cc - 576];
            g_bias2[cc] = bv;
        }
    }
}

// ---------------------------------------------------------------------------
// mma.sync fp16 GEMM, 2-stage cp.async smem pipeline + double-buffered
// register fragments.  MODE 0: GEMM1 (relu-fp16 -> MID for cols<768; fp32
// h_base spill for rows<MODROWS cols<256; fp32 tail).  MODE 1: GEMM2
// block-diagonal, per-tile K-windows, |out| fp16 -> g_W1F16.
// ---------------------------------------------------------------------------
#define SROW    144
#define OF_A    0
#define OF_B    (128 * SROW)            // 18432
#define STAGE   (OF_B + 64 * SROW)      // 27648
#define SMTOT   (2 * STAGE)             // 55296

__device__ __forceinline__ void load_a_frags(uint32_t stb, int ks, uint32_t a[2][4],
                                             int wm, int lane) {
    #pragma unroll
    for (int mt = 0; mt < 2; mt++) {
        int ar = wm * 32 + mt * 16 + (lane & 15);
        int ak = ks * 16 + (lane >> 4) * 8;
        ldsm_x4(a[mt], stb + OF_A + (uint32_t)(ar * SROW + ak * 2));
    }
}
__device__ __forceinline__ void load_b_frags(uint32_t stb, int ks, uint32_t b[4][2],
                                             int wn, int lane) {
    #pragma unroll
    for (int jp = 0; jp < 2; jp++) {
        int tilei = lane >> 3, rin = lane & 7;
        int nrow = wn * 32 + jp * 16 + (tilei >> 1) * 8 + rin;
        int kof  = ks * 16 + (tilei & 1) * 8;
        uint32_t r[4];
        ldsm_x4(r, stb + OF_B + (uint32_t)(nrow * SROW + kof * 2));
        b[jp*2][0] = r[0]; b[jp*2][1] = r[1];
        b[jp*2+1][0] = r[2]; b[jp*2+1][1] = r[3];
    }
}

template <int MODE>
__global__ void __launch_bounds__(256)
gemm_mma(const __half* __restrict__ A, int lda,
         const __half* __restrict__ B, int ldb,
         const float* __restrict__ bias,
         float* __restrict__ C, int ldc, int Nvalid, int Kfull)
{
    extern __shared__ char smem[];
    const uint32_t sb = smem_u32(smem);
    const int tid  = threadIdx.x;
    const int w    = tid >> 5;
    const int lane = tid & 31;
    const int wm   = w & 3;
    const int wn   = w >> 2;
    const int bm   = blockIdx.y * 128;
    const int bn   = blockIdx.x * 64;

    int kb = 0, klen = Kfull;
    if (MODE == 1) {
        if (bn + 64 <= 512)      { kb = 256; klen = 256; }   // dense w1 tiles
        else if (bn < 576)       { kb = 256; klen = 512; }   // mixed w1/w2 tile
        else                     { kb = 0;   klen = 256; }   // w00 tile
    }

    float acc[2][4][4];
    #pragma unroll
    for (int mt = 0; mt < 2; mt++)
        #pragma unroll
        for (int nt = 0; nt < 4; nt++)
            #pragma unroll
            for (int i = 0; i < 4; i++) acc[mt][nt][i] = 0.f;

    const int nch = klen >> 6;
    const int arow = tid >> 3, asec = tid & 7;

    #define ISSUE_LOADS(c_, s_) do {                                             \
        const int k0_ = kb + ((c_) << 6);                                        \
        const uint32_t base_ = sb + (s_) * STAGE;                                \
        _Pragma("unroll")                                                        \
        for (int i = 0; i < 4; i++) {                                            \
            int row_ = arow + i * 32;                                            \
            uint32_t so_ = base_ + row_ * SROW + asec * 16;                      \
            const size_t go_ = (size_t)(bm + row_) * lda + k0_ + asec * 8;       \
            CP_ASYNC16(so_ + OF_A, (const char*)(A + go_));                      \
        }                                                                        \
        _Pragma("unroll")                                                        \
        for (int i = 0; i < 2; i++) {                                            \
            int row_ = arow + i * 32;                                            \
            uint32_t so_ = base_ + row_ * SROW + asec * 16;                      \
            const size_t go_ = (size_t)(bn + row_) * ldb + k0_ + asec * 8;       \
            CP_ASYNC16(so_ + OF_B, (const char*)(B + go_));                      \
        }                                                                        \
        CP_COMMIT();                                                             \
    } while (0)

    ISSUE_LOADS(0, 0);

    for (int c = 0; c < nch; c++) {
        if (c + 1 < nch) { ISSUE_LOADS(c + 1, (c + 1) & 1); CP_WAIT(1); }
        else             { CP_WAIT(0); }
        __syncthreads();

        const uint32_t stb = sb + (c & 1) * STAGE;

        uint32_t ah[2][2][4], bh[2][4][2];
        load_a_frags(stb, 0, ah[0], wm, lane);
        load_b_frags(stb, 0, bh[0], wn, lane);

        #pragma unroll
        for (int ks = 0; ks < 4; ks++) {
            const int cur = ks & 1;
            if (ks < 3) {
                load_a_frags(stb, ks + 1, ah[cur ^ 1], wm, lane);
                load_b_frags(stb, ks + 1, bh[cur ^ 1], wn, lane);
            }
            #pragma unroll
            for (int mt = 0; mt < 2; mt++)
                #pragma unroll
                for (int nt = 0; nt < 4; nt++)
                    mma_f16(acc[mt][nt], ah[cur][mt], bh[cur][nt]);
        }
        __syncthreads();
    }

    // Epilogue
    const int trow  = lane >> 2;
    const int tcol2 = (lane & 3) * 2;
    #pragma unroll
    for (int mt = 0; mt < 2; mt++) {
        #pragma unroll
        for (int nt = 0; nt < 4; nt++) {
            int col = bn + wn * 32 + nt * 8 + tcol2;
            float bv0 = bias[col], bv1 = bias[col + 1];
            #pragma unroll
            for (int half = 0; half < 2; half++) {
                int row = bm + wm * 32 + mt * 16 + trow + half * 8;
                float v0 = acc[mt][nt][half * 2 + 0] + bv0;
                float v1 = acc[mt][nt][half * 2 + 1] + bv1;
                if (MODE == 0) {
                    if (col < 768) {
                        ((uint32_t*)g_MID)[((size_t)row * MIDW + col) >> 1] =
                            pack_h2(fmaxf(v0, 0.f), fmaxf(v1, 0.f));
                        if (col < 256 && row < MODROWS)
                            *(float2*)(C + (size_t)row * ldc + col) = make_float2(v0, v1);
                    } else if (col < Nvalid) {
                        *(float2*)(C + (size_t)row * ldc + col) = make_float2(v0, v1);
                    }
                } else {
                    if (col < Nvalid)
                        ((uint32_t*)g_W1F16)[((size_t)row * N2P2 + col) >> 1] =
                            pack_h2(fabsf(v0), fabsf(v1));
                }
            }
        }
    }
}

// ---------------------------------------------------------------------------
// Final fused kernel: one warp per row.  w00 common from W1F16; mod path
// (rows < MODROWS only) recomputed in fp32 from the H1 h_base spill.
// ---------------------------------------------------------------------------
__global__ void __launch_bounds__(256)
final_kernel(const float* __restrict__ qvals,
             const int*   __restrict__ cr,
             const float* __restrict__ w00_l2_W,  // (256,4)
             const float* __restrict__ w00_l2_b,  // (4)
             const float* __restrict__ b2_l2_W,   // (32,1)
             const float* __restrict__ b2_l2_b,   // (1)
             float* __restrict__ out)
{
    __shared__ float s_q[8][NAa];

    const int w = threadIdx.x >> 5;
    const int l = threadIdx.x & 31;
    const int r = blockIdx.x * 8 + w;
    const int b = r >> 6;                 // batch index (T = 64)
    const float* __restrict__ row = g_H1 + (size_t)r * NCAT;

    if (l < NAa) s_q[w][l] = qvals[r * NAa + l];
    __syncwarp();

    const bool mod = (b < NVv);
    const __half* __restrict__ w1r = g_W1F16 + (size_t)r * N2P2;

    // w00 common (|.| with bias) from GEMM2
    float w0c[4];
    #pragma unroll
    for (int o = 0; o < 4; o++) w0c[o] = __half2float(w1r[576 + o]);

    // w00 modified: fp32 recompute, only rows < MODROWS
    float w0m[4] = {0.f, 0.f, 0.f, 0.f};
    if (mod) {
        float accm[4] = {0.f, 0.f, 0.f, 0.f};
        for (int kk = l; kk < Hh; kk += 32) {
            float hm = fmaxf(row[kk] + g_hdelta[kk], 0.f);
            float4 wv = *(const float4*)(w00_l2_W + kk * 4);
            accm[0] += hm * wv.x; accm[1] += hm * wv.y;
            accm[2] += hm * wv.z; accm[3] += hm * wv.w;
        }
        #pragma unroll
        for (int o = 0; o < 4; o++) {
            #pragma unroll
            for (int off = 16; off; off >>= 1)
                accm[o] += __shfl_xor_sync(0xffffffffu, accm[o], off);
            w0m[o] = fabsf(accm[o] + w00_l2_b[o]);
        }
    }

    float w2a = __half2float(w1r[N2 + l]);

    float xb2 = fmaxf(row[812 + l], 0.f) * b2_l2_W[l];
    #pragma unroll
    for (int off = 16; off; off >>= 1) xb2 += __shfl_xor_sync(0xffffffffu, xb2, off);
    float b2 = xb2 + b2_l2_b[0];

    float b1v = row[780 + l];

    float gq_l;
    if (l < NVv) {
        const int* __restrict__ crr = cr + (size_t)r * (Kk * NVv);
        float g = 0.f;
        #pragma unroll
        for (int k = 0; k < Kk; k++) {
            int idx = crr[k * NVv + l];
            float wk = (mod && l == b) ? w0m[k] : w0c[k];
            g += s_q[w][idx] * wk;
        }
        g += row[779];
        if (mod && l == b) g += g_gdelta[0];
        gq_l = g;
    } else {
        float oth = row[778];
        #pragma unroll
        for (int a = 0; a < NAa; a++) oth += s_q[w][a] * row[768 + a];
        gq_l = oth;
    }

    // hidden = elu(gq @ |w1| + b1) — w1r already |.|
    float accH = b1v;
    #pragma unroll
    for (int v = 0; v <= NVv; v++) {
        float gqv = __shfl_sync(0xffffffffu, gq_l, v);
        accH += gqv * __half2float(w1r[v * Ee + l]);
    }
    float hidden = (accH > 0.f) ? accH : expm1f(accH);

    float part = hidden * w2a;
    #pragma unroll
    for (int off = 16; off; off >>= 1) part += __shfl_xor_sync(0xffffffffu, part, off);
    if (l == 0) out[r] = part + b2;
}

// ---------------------------------------------------------------------------
extern "C" void kernel_launch(void* const* d_in, const int* in_sizes, int n_in,
                              void* d_out, int out_size)
{
    const float* qvals    = (const float*)d_in[0];
    const int*   cr       = (const int*)  d_in[1];
    const float* states   = (const float*)d_in[2];
    const float* w00_l1_W = (const float*)d_in[3];
    const float* w00_l1_b = (const float*)d_in[4];
    const float* w00_l2_W = (const float*)d_in[5];
    const float* w00_l2_b = (const float*)d_in[6];
    const float* b00_W    = (const float*)d_in[7];
    const float* b00_b    = (const float*)d_in[8];
    const float* w01_W    = (const float*)d_in[9];
    const float* w01_b    = (const float*)d_in[10];
    const float* b01_W    = (const float*)d_in[11];
    const float* b01_b    = (const float*)d_in[12];
    const float* w1_l1_W  = (const float*)d_in[13];
    const float* w1_l1_b  = (const float*)d_in[14];
    const float* w1_l2_W  = (const float*)d_in[15];
    const float* w1_l2_b  = (const float*)d_in[16];
    const float* b1_W     = (const float*)d_in[17];
    const float* b1_b     = (const float*)d_in[18];
    const float* w2_l1_W  = (const float*)d_in[19];
    const float* w2_l1_b  = (const float*)d_in[20];
    const float* w2_l2_W  = (const float*)d_in[21];
    const float* w2_l2_b  = (const float*)d_in[22];
    const float* b2_l1_W  = (const float*)d_in[23];
    const float* b2_l1_b  = (const float*)d_in[24];
    const float* b2_l2_W  = (const float*)d_in[25];
    const float* b2_l2_b  = (const float*)d_in[26];
    float* out = (float*)d_out;

    static int attr_done = 0;
    if (!attr_done) {
        cudaFuncSetAttribute(gemm_mma<0>, cudaFuncAttributeMaxDynamicSharedMemorySize, SMTOT);
        cudaFuncSetAttribute(gemm_mma<1>, cudaFuncAttributeMaxDynamicSharedMemorySize, SMTOT);
        attr_done = 1;
    }

    float *H1, *biascat, *bias2;
    __half *ST, *MID, *BT, *B2T;
    cudaGetSymbolAddress((void**)&H1,      g_H1);
    cudaGetSymbolAddress((void**)&biascat, g_biascat);
    cudaGetSymbolAddress((void**)&bias2,   g_bias2);
    cudaGetSymbolAddress((void**)&ST,      g_ST);
    cudaGetSymbolAddress((void**)&MID,     g_MID);
    cudaGetSymbolAddress((void**)&BT,      g_BT);
    cudaGetSymbolAddress((void**)&B2T,     g_B2T);

    // 1) merged precompute
    prep_kernel<<<(N_PREP + 255) / 256, 256>>>(
        states,
        w00_l1_W, w00_l1_b, w1_l1_W, w1_l1_b, w2_l1_W, w2_l1_b,
        w01_W, w01_b, b01_W, b01_b, b00_W, b00_b, b1_W, b1_b, b2_l1_W, b2_l1_b,
        w1_l2_W, w1_l2_b, w2_l2_W, w2_l2_b, w00_l2_W, w00_l2_b);

    // 2) GEMM1: relu-fp16 -> MID (cols<768), fp32 h_base spill rows<1024, fp32 tail
    {
        dim3 grid(NCATP / 64, ROWS / 128);
        gemm_mma<0><<<grid, 256, SMTOT>>>(ST, SDd, BT, SDd,
                                          biascat, H1, NCAT, NCAT, SDd);
    }

    // 3) GEMM2 (block-diagonal, per-tile K-windows): |out| fp16 -> g_W1F16
    {
        dim3 grid(N2P2 / 64, ROWS / 128);
        gemm_mma<1><<<grid, 256, SMTOT>>>(MID, MIDW, B2T, K2,
                                          bias2, nullptr, 0, N2V, K2);
    }

    // 4) fused epilogue
    final_kernel<<<ROWS / 8, 256>>>(qvals, cr, w00_l2_W, w00_l2_b,
                                    b2_l2_W, b2_l2_b, out);
}